// round 1
// baseline (speedup 1.0000x reference)
#include <cuda_runtime.h>
#include <cstdint>

// WholeMask: paste B*K 28x28 masks into 512x512 canvases (nearest-neighbor
// over the rounded+clipped bbox), zero elsewhere and for k >= counts[b].
//
// Pure HBM-write-bound: 134 MB output. Strategy: one grid.x per (b,k) slice,
// grid.y splits rows; mask tile + per-x source-column LUT in shared; float4
// streaming stores.

#define MH 28
#define MW 28
#define IMG 512

__global__ __launch_bounds__(512, 2)
void wholemask_kernel(const float* __restrict__ bboxess,
                      const int*   __restrict__ counts,
                      const float* __restrict__ maskss,
                      float*       __restrict__ out,
                      int Kk)
{
    const int slice = blockIdx.x;          // b*K + k
    const int b = slice / Kk;
    const int k = slice - b * Kk;

    __shared__ float smask[MH * MW];       // 3136 B
    __shared__ int   ssx[IMG];             // 2048 B

    const int tid = threadIdx.y * blockDim.x + threadIdx.x;   // 0..511

    const bool valid = (k < counts[b]);

    // Rounded + clipped box (all threads compute redundantly; cheap).
    const float4 bb = reinterpret_cast<const float4*>(bboxess)[slice];
    int y1 = __float2int_rn(bb.x);   // round-half-even == jnp.round
    int x1 = __float2int_rn(bb.y);
    int y2 = __float2int_rn(bb.z);
    int x2 = __float2int_rn(bb.w);
    y1 = min(max(y1, 0), IMG - 1);
    x1 = min(max(x1, 0), IMG - 1);
    y2 = min(max(y2, y1 + 1), IMG);
    x2 = min(max(x2, x1 + 1), IMG);
    const int h = y2 - y1;
    const int w = x2 - x1;

    if (valid) {
        // Stage mask tile into shared.
        const float* msrc = maskss + (size_t)slice * (MH * MW);
        for (int i = tid; i < MH * MW; i += 512)
            smask[i] = msrc[i];
        // Per-x source column LUT: sx = clip((x - x1)*MW / w, 0, MW-1).
        // (Truncating div differs from floor only for x < x1, where the
        //  clamp to 0 makes them agree; pixels there are zeroed anyway.)
        {
            const int x = tid;               // 512 threads == 512 columns
            int sx = ((x - x1) * MW) / w;
            ssx[x] = min(max(sx, 0), MW - 1);
        }
        __syncthreads();
    }

    // Each block writes 64 rows of this slice: rows [blockIdx.y*64, +64).
    float* obase = out + (size_t)slice * (IMG * IMG);
    const int xq = threadIdx.x * 4;          // float4 column start, 0..508

    #pragma unroll 4
    for (int yy = 0; yy < 64; yy += 4) {
        const int y = blockIdx.y * 64 + yy + threadIdx.y;
        float4 v = make_float4(0.f, 0.f, 0.f, 0.f);
        if (valid && y >= y1 && y < y2) {
            int sy = ((y - y1) * MH) / h;
            sy = min(max(sy, 0), MH - 1);
            const float* mrow = smask + sy * MW;
            if (xq     >= x1 && xq     < x2) v.x = mrow[ssx[xq]];
            if (xq + 1 >= x1 && xq + 1 < x2) v.y = mrow[ssx[xq + 1]];
            if (xq + 2 >= x1 && xq + 2 < x2) v.z = mrow[ssx[xq + 2]];
            if (xq + 3 >= x1 && xq + 3 < x2) v.w = mrow[ssx[xq + 3]];
        }
        // Streaming store: no reuse, keep it out of L2 as much as possible.
        __stcs(reinterpret_cast<float4*>(obase + (size_t)y * IMG + xq), v);
    }
}

extern "C" void kernel_launch(void* const* d_in, const int* in_sizes, int n_in,
                              void* d_out, int out_size)
{
    const float* bboxess = (const float*)d_in[0];   // (B,K,4) f32
    const int*   counts  = (const int*)  d_in[1];   // (B,1)   i32
    const float* maskss  = (const float*)d_in[2];   // (B,K,1,28,28) f32

    const int BK = in_sizes[0] / 4;                 // B*K
    const int Bv = in_sizes[1];                     // B
    const int Kk = BK / Bv;                         // K

    dim3 block(128, 4);           // 128 float4 lanes x 4 rows
    dim3 grid(BK, IMG / 64);      // 128 slices x 8 row-chunks
    wholemask_kernel<<<grid, block>>>(bboxess, counts, maskss,
                                      (float*)d_out, Kk);
}